// round 1
// baseline (speedup 1.0000x reference)
#include <cuda_runtime.h>
#include <cuda_bf16.h>

// out[b,s,h,d] = cos(x[b,s,h,d]) * cos(params[h,d,0])
// x: [8, 8192, 1024] fp32 (64M elems), params: [16, 64, 3] fp32.
// Channel index c = (h*64+d) = linear_index % 1024. ry[c] = cos(params[c*3]).
//
// HBM-bound elementwise: float4 loads/stores, per-block shared ry table.

#define THREADS 256
#define CHAN4 256  // 1024 channels / 4 per float4

__global__ __launch_bounds__(THREADS)
void qa_cos_kernel(const float4* __restrict__ x,
                   const float* __restrict__ params,
                   float4* __restrict__ out,
                   int n4)
{
    __shared__ float4 s_ry[CHAN4];

    int tid = threadIdx.x;
    // Each thread fills one float4 of the ry table (256 threads == 256 entries).
    {
        int c = tid * 4;
        float4 r;
        r.x = cosf(params[(c + 0) * 3]);
        r.y = cosf(params[(c + 1) * 3]);
        r.z = cosf(params[(c + 2) * 3]);
        r.w = cosf(params[(c + 3) * 3]);
        s_ry[tid] = r;
    }
    __syncthreads();

    int idx = blockIdx.x * THREADS + tid;
    if (idx < n4) {
        float4 v = x[idx];
        // 1024 channels = 256 float4 groups; group index repeats mod 256.
        float4 r = s_ry[idx & (CHAN4 - 1)];
        float4 o;
        o.x = __cosf(v.x) * r.x;
        o.y = __cosf(v.y) * r.y;
        o.z = __cosf(v.z) * r.z;
        o.w = __cosf(v.w) * r.w;
        out[idx] = o;
    }
}

extern "C" void kernel_launch(void* const* d_in, const int* in_sizes, int n_in,
                              void* d_out, int out_size)
{
    const float* x      = (const float*)d_in[0];
    const float* params = (const float*)d_in[1];
    float* out          = (float*)d_out;

    int n  = in_sizes[0];      // 67,108,864
    int n4 = n >> 2;           // 16,777,216 float4s
    int grid = (n4 + THREADS - 1) / THREADS;  // 65,536 blocks

    qa_cos_kernel<<<grid, THREADS>>>((const float4*)x, params, (float4*)out, n4);
}

// round 2
// speedup vs baseline: 1.1496x; 1.1496x over previous
#include <cuda_runtime.h>
#include <cuda_bf16.h>

// out[b,s,h,d] = cos(x[b,s,h,d]) * cos(params[h,d,0])
// x: [8, 8192, 1024] fp32 (64M elems = 16M float4), params: [16, 64, 3] fp32.
//
// channel4 = float4_index % 256. With 256 threads/block and all strides
// multiples of 256, channel4 == threadIdx.x for every element a thread
// touches -> ry lives in 4 registers per thread. No shared memory.
//
// 8 float4 per thread, loads batched front (MLP=8), pure HBM stream.

#define THREADS 256
#define UNROLL  8

__global__ __launch_bounds__(THREADS)
void qa_cos_kernel(const float4* __restrict__ x,
                   const float* __restrict__ params,
                   float4* __restrict__ out,
                   int n4)
{
    const int tid = threadIdx.x;

    // Per-thread constant ry (channel group == tid).
    const int c = tid * 4;
    float4 r;
    r.x = cosf(params[(c + 0) * 3]);
    r.y = cosf(params[(c + 1) * 3]);
    r.z = cosf(params[(c + 2) * 3]);
    r.w = cosf(params[(c + 3) * 3]);

    const int base = blockIdx.x * (THREADS * UNROLL) + tid;

    if (base + (UNROLL - 1) * THREADS < n4) {
        // Fast path: all 8 in range. Batch loads for MLP.
        float4 v[UNROLL];
#pragma unroll
        for (int i = 0; i < UNROLL; i++)
            v[i] = x[base + i * THREADS];
#pragma unroll
        for (int i = 0; i < UNROLL; i++) {
            float4 o;
            o.x = __cosf(v[i].x) * r.x;
            o.y = __cosf(v[i].y) * r.y;
            o.z = __cosf(v[i].z) * r.z;
            o.w = __cosf(v[i].w) * r.w;
            out[base + i * THREADS] = o;
        }
    } else {
#pragma unroll
        for (int i = 0; i < UNROLL; i++) {
            int idx = base + i * THREADS;
            if (idx < n4) {
                float4 v = x[idx];
                float4 o;
                o.x = __cosf(v.x) * r.x;
                o.y = __cosf(v.y) * r.y;
                o.z = __cosf(v.z) * r.z;
                o.w = __cosf(v.w) * r.w;
                out[idx] = o;
            }
        }
    }
}

extern "C" void kernel_launch(void* const* d_in, const int* in_sizes, int n_in,
                              void* d_out, int out_size)
{
    const float* x      = (const float*)d_in[0];
    const float* params = (const float*)d_in[1];
    float* out          = (float*)d_out;

    int n  = in_sizes[0];          // 67,108,864
    int n4 = n >> 2;               // 16,777,216 float4s
    int per_block = THREADS * UNROLL;
    int grid = (n4 + per_block - 1) / per_block;   // 8192 blocks

    qa_cos_kernel<<<grid, THREADS>>>((const float4*)x, params, (float4*)out, n4);
}

// round 3
// speedup vs baseline: 1.1638x; 1.0124x over previous
#include <cuda_runtime.h>
#include <cuda_bf16.h>

// out[b,s,h,d] = cos(x[b,s,h,d]) * cos(params[h,d,0])
// x: [8, 8192, 1024] fp32 = 16,777,216 float4; params: [16, 64, 3] fp32.
//
// channel4 = float4_index % 256 == threadIdx.x (all strides are multiples
// of 256) -> ry in 4 registers per thread, computed once from params.
//
// Pure HBM stream: 16 float4 per thread, all loads front-batched (MLP=16),
// streaming cache hints (no reuse -> evict-first in L2).

#define THREADS 256
#define UNROLL  16

__global__ __launch_bounds__(THREADS)
void qa_cos_kernel(const float4* __restrict__ x,
                   const float* __restrict__ params,
                   float4* __restrict__ out,
                   int n4)
{
    const int tid = threadIdx.x;

    // Per-thread constant ry (channel group == tid).
    const int c = tid * 4;
    float4 r;
    r.x = cosf(params[(c + 0) * 3]);
    r.y = cosf(params[(c + 1) * 3]);
    r.z = cosf(params[(c + 2) * 3]);
    r.w = cosf(params[(c + 3) * 3]);

    const int base = blockIdx.x * (THREADS * UNROLL) + tid;

    if (base + (UNROLL - 1) * THREADS < n4) {
        float4 v[UNROLL];
#pragma unroll
        for (int i = 0; i < UNROLL; i++)
            v[i] = __ldcs(&x[base + i * THREADS]);
#pragma unroll
        for (int i = 0; i < UNROLL; i++) {
            float4 o;
            o.x = __cosf(v[i].x) * r.x;
            o.y = __cosf(v[i].y) * r.y;
            o.z = __cosf(v[i].z) * r.z;
            o.w = __cosf(v[i].w) * r.w;
            __stcs(&out[base + i * THREADS], o);
        }
    } else {
#pragma unroll
        for (int i = 0; i < UNROLL; i++) {
            int idx = base + i * THREADS;
            if (idx < n4) {
                float4 v = __ldcs(&x[idx]);
                float4 o;
                o.x = __cosf(v.x) * r.x;
                o.y = __cosf(v.y) * r.y;
                o.z = __cosf(v.z) * r.z;
                o.w = __cosf(v.w) * r.w;
                __stcs(&out[idx], o);
            }
        }
    }
}

extern "C" void kernel_launch(void* const* d_in, const int* in_sizes, int n_in,
                              void* d_out, int out_size)
{
    const float* x      = (const float*)d_in[0];
    const float* params = (const float*)d_in[1];
    float* out          = (float*)d_out;

    int n  = in_sizes[0];          // 67,108,864
    int n4 = n >> 2;               // 16,777,216 float4s
    int per_block = THREADS * UNROLL;
    int grid = (n4 + per_block - 1) / per_block;   // 4096 blocks

    qa_cos_kernel<<<grid, THREADS>>>((const float4*)x, params, (float4*)out, n4);
}